// round 15
// baseline (speedup 1.0000x reference)
#include <cuda_runtime.h>
#include <math.h>

#define LOUT 2048
#define NFFT 4096
#define CLEN 32
#define NCH  128
#define TPB  128

// per batch: n0, n1, n2, tr, det (stride 8 floats)
__device__ float g_coef[4096 * 8];

// ---------------------------------------------------------------------------
// Coefficient kernel: closed-form circuit solve (fp64, tiny).
// ---------------------------------------------------------------------------
__global__ void coeff_kernel(const float* __restrict__ cond,
                             const float* __restrict__ cw,
                             const float* __restrict__ cb,
                             const float* __restrict__ a_rg,
                             const float* __restrict__ a_r1,
                             const float* __restrict__ a_c1,
                             const float* __restrict__ a_c2, int B) {
    int b = blockIdx.x * blockDim.x + threadIdx.x;
    if (b >= B) return;

    const double T = 1.0 / 44100.0;
    double sRG = (double)(1.f / (1.f + expf(-a_rg[0])));
    double sR1 = (double)(1.f / (1.f + expf(-a_r1[0])));
    double sC1 = (double)(1.f / (1.f + expf(-a_c1[0])));
    double sC2 = (double)(1.f / (1.f + expf(-a_c2[0])));
    double RG = (0.9 + 0.2 * sRG) * 1.0e6;
    double R1 = (0.99 + 0.02 * sR1) * 4.7e5;
    double C1 = (0.9 + 0.2 * sC1) * 3.3e-9;
    double C2 = (0.9 + 0.2 * sC2) * 1.0e-9;
    double Gr = 1.0 / R1, g1 = 2.0 * C1 / T, g2 = 2.0 * C2 / T;
    double G = g1 + Gr, h = g1 / G, iG = 1.0 / G, ig2 = 1.0 / g2;

    double Q00 = iG + ig2, Q01 = -ig2, Q11 = ig2;
    double Ux00 = -iG, Ux01 = 0.0, Ux10 = -ig2, Ux11 = ig2;
    double Ao00 = 2.0 * g1 * iG - 1.0, Ao11 = 1.0;
    double Uo0 = -ig2, Uo1 = ig2;
    double Uu0 = h;
    double Do1 = ig2;
    double Bo0 = 2.0 * g1 * (1.0 - h);
    double W000 = -2.0 * g1 * iG;
    double W010 = -2.0, W011 = 2.0;

    float zf  = cond[b] * cw[0] + cb[0];
    float pot = 1.f / (1.f + expf(-zf));
    float pf  = (powf(10.f, pot) - 1.f) / 9.f;
    pf = fminf(fmaxf(pf, 1e-4f), 1.f - 1e-4f);
    double p = (double)pf;

    double r00 = (1.0 - p) * RG + Q00, r01 = Q01, r11 = p * RG + Q11;
    double id  = 1.0 / (r00 * r11 - r01 * r01);
    double S00 = r11 * id, S01 = -r01 * id, S11 = r00 * id;

    double W00 = W000 * S00;
    double W01 = W000 * S01;
    double W10 = W010 * S00 + W011 * S01;
    double W11 = W010 * S01 + W011 * S11;

    double A00 = Ao00 - (W00 * Ux00 + W01 * Ux01);
    double A01 =       - (W00 * Ux10 + W01 * Ux11);
    double A10 =       - (W10 * Ux00 + W11 * Ux01);
    double A11 = Ao11 - (W10 * Ux10 + W11 * Ux11);
    double Bm0 = Bo0 - W00 * Uu0;
    double Bm1 =     - W10 * Uu0;
    double V0  = Uo0 * S00 + Uo1 * S01;
    double V1  = Uo0 * S01 + Uo1 * S11;
    double Dm0 =       - (V0 * Ux00 + V1 * Ux01);
    double Dm1 = Do1   - (V0 * Ux10 + V1 * Ux11);
    double Em  = -(V0 * Uu0);

    double tr  = A00 + A11;
    double det = A00 * A11 - A01 * A10;
    double E00 = A00 - Bm0 * Dm0, E01 = A01 - Bm0 * Dm1;
    double E10 = A10 - Bm1 * Dm0, E11 = A11 - Bm1 * Dm1;
    double trE = E00 + E11, detE = E00 * E11 - E01 * E10;

    float* cf = g_coef + b * 8;
    cf[0] = (float)Em;
    cf[1] = (float)(-trE - (Em - 1.0) * tr);
    cf[2] = (float)(detE + (Em - 1.0) * det);
    cf[3] = (float)tr;
    cf[4] = (float)det;
}

// ---------------------------------------------------------------------------
// Filter kernel: exact circular backward biquad via 128-chunk affine scan +
// 64-chunk replay. y overlaid into the first half of the st buffer:
//   replay reads padded idx >= IDX5(2048)=2112, writes idx <= IDX5(2047)=2110.
// Global side uses float4 (aligned); shared side is scalar (pad breaks 16B
// alignment of the padded index — that was the R4 trap).
// ---------------------------------------------------------------------------
#define IDX5(n) ((n) + ((n) >> 5))

__global__ void __launch_bounds__(TPB)
filter_kernel(const float* __restrict__ x, const float* __restrict__ state,
              float* __restrict__ out) {
    __shared__ float st[4226];            // IDX5(4097)=4225
    __shared__ float scanArr[NCH][6];
    __shared__ float warpTot[4][6];

    int b = blockIdx.x, tid = threadIdx.x;
    const float* cf = g_coef + b * 8;
    float n0 = cf[0], n1 = cf[1], n2 = cf[2], tr = cf[3], dt = cf[4];

    const float* stt = state + (size_t)b * NFFT + LOUT;  // state tail
    const float* xb  = x + (size_t)b * LOUT;

    // load periodic buffer: LDG.128, scalar STS (padded idx not 16B-aligned)
#pragma unroll
    for (int it = 0; it < 8; it++) {
        int n = (tid + it * TPB) * 4;
        float4 v = (n < LOUT) ? *(const float4*)(stt + n)
                              : *(const float4*)(xb + n - LOUT);
        int i0 = IDX5(n);                 // n..n+3 stay in one pad group
        st[i0] = v.x; st[i0 + 1] = v.y; st[i0 + 2] = v.z; st[i0 + 3] = v.w;
    }
    if (tid < 2) st[IDX5(NFFT + tid)] = stt[tid];
    __syncthreads();

    // Pass 1: chunk c = tid, 32 backward steps, zero IC, track affine map.
    int c = tid;
    int nhi = NFFT - 1 - CLEN * c;        // nhi ≡ 31 (mod 32): chunk in one pad group
    int off = IDX5(nhi);
    float v1 = st[IDX5(nhi + 1)], v2 = st[IDX5(nhi + 2)];
    float pa = 0.f, pb = 0.f;
    float ma0 = 1.f, ma1 = 0.f, mb0 = 0.f, mb1 = 1.f;
#pragma unroll
    for (int i = 0; i < CLEN; i++) {
        float v0 = st[off - i];
        float s  = fmaf(n0, v0, fmaf(n1, v1, n2 * v2));
        float pc = fmaf(tr, pa, fmaf(-dt, pb, s));
        float t0 = fmaf(tr, ma0, -dt * mb0);
        float t1 = fmaf(tr, ma1, -dt * mb1);
        mb0 = ma0; mb1 = ma1; ma0 = t0; ma1 = t1;
        pb = pa; pa = pc;
        v2 = v1; v1 = v0;
    }

    // Intra-warp inclusive affine scan (compose: self ∘ left).
    const unsigned fullm = 0xffffffffu;
    int lane = tid & 31;
#pragma unroll
    for (int d = 1; d < 32; d <<= 1) {
        float la0 = __shfl_up_sync(fullm, ma0, d);
        float la1 = __shfl_up_sync(fullm, ma1, d);
        float lb0 = __shfl_up_sync(fullm, mb0, d);
        float lb1 = __shfl_up_sync(fullm, mb1, d);
        float lp0 = __shfl_up_sync(fullm, pa, d);
        float lp1 = __shfl_up_sync(fullm, pb, d);
        if (lane >= d) {
            float na0 = ma0 * la0 + ma1 * lb0;
            float na1 = ma0 * la1 + ma1 * lb1;
            float nb0 = mb0 * la0 + mb1 * lb0;
            float nb1 = mb0 * la1 + mb1 * lb1;
            float np0 = ma0 * lp0 + ma1 * lp1 + pa;
            float np1 = mb0 * lp0 + mb1 * lp1 + pb;
            ma0 = na0; ma1 = na1; mb0 = nb0; mb1 = nb1; pa = np0; pb = np1;
        }
    }
    int w = tid >> 5;
    if (lane == 31) {
        warpTot[w][0] = ma0; warpTot[w][1] = ma1;
        warpTot[w][2] = mb0; warpTot[w][3] = mb1;
        warpTot[w][4] = pa;  warpTot[w][5] = pb;
    }
    __syncthreads();

    // cross-warp composition
    if (w > 0) {
        float LA0 = warpTot[0][0], LA1 = warpTot[0][1];
        float LB0 = warpTot[0][2], LB1 = warpTot[0][3];
        float LP0 = warpTot[0][4], LP1 = warpTot[0][5];
        for (int ww = 1; ww < w; ww++) {
            float t0 = warpTot[ww][0], t1 = warpTot[ww][1];
            float t2 = warpTot[ww][2], t3 = warpTot[ww][3];
            float t4 = warpTot[ww][4], t5 = warpTot[ww][5];
            float nA0 = t0 * LA0 + t1 * LB0, nA1 = t0 * LA1 + t1 * LB1;
            float nB0 = t2 * LA0 + t3 * LB0, nB1 = t2 * LA1 + t3 * LB1;
            float nP0 = t0 * LP0 + t1 * LP1 + t4;
            float nP1 = t2 * LP0 + t3 * LP1 + t5;
            LA0 = nA0; LA1 = nA1; LB0 = nB0; LB1 = nB1; LP0 = nP0; LP1 = nP1;
        }
        float na0 = ma0 * LA0 + ma1 * LB0;
        float na1 = ma0 * LA1 + ma1 * LB1;
        float nb0 = mb0 * LA0 + mb1 * LB0;
        float nb1 = mb0 * LA1 + mb1 * LB1;
        float np0 = ma0 * LP0 + ma1 * LP1 + pa;
        float np1 = mb0 * LP0 + mb1 * LP1 + pb;
        ma0 = na0; ma1 = na1; mb0 = nb0; mb1 = nb1; pa = np0; pb = np1;
    }
    scanArr[c][0] = ma0; scanArr[c][1] = ma1;
    scanArr[c][2] = mb0; scanArr[c][3] = mb1;
    scanArr[c][4] = pa;  scanArr[c][5] = pb;
    __syncthreads();

    // Replay: threads c<64 solve the periodic fixed point, get exact chunk IC,
    // re-run 32 steps and write y into st[IDX5(0..2047)] (disjoint from reads).
    if (c < 64) {
        float F00 = scanArr[NCH - 1][0], F01 = scanArr[NCH - 1][1];
        float F10 = scanArr[NCH - 1][2], F11 = scanArr[NCH - 1][3];
        float Pt0 = scanArr[NCH - 1][4], Pt1 = scanArr[NCH - 1][5];
        float aa = 1.f - F00, bb = -F01, cc = -F10, dd = 1.f - F11;
        float inv = 1.f / (aa * dd - bb * cc);
        float w0 = (dd * Pt0 - bb * Pt1) * inv;
        float w1 = (-cc * Pt0 + aa * Pt1) * inv;

        float vx, vy;
        if (c == 0) { vx = w0; vy = w1; }
        else {
            float e0 = scanArr[c - 1][0], e1 = scanArr[c - 1][1];
            float e2 = scanArr[c - 1][2], e3 = scanArr[c - 1][3];
            float e4 = scanArr[c - 1][4], e5 = scanArr[c - 1][5];
            vx = e0 * w0 + e1 * w1 + e4;
            vy = e2 * w0 + e3 * w1 + e5;
        }

        int rb  = IDX5(nhi);
        float r1 = st[IDX5(nhi + 1)], r2 = st[IDX5(nhi + 2)];
        float ya = vx, yb = vy;
        int kbase = IDX5(nhi - LOUT);     // same pad group (nhi-2048 ≡ 31 mod 32)
#pragma unroll
        for (int i = 0; i < CLEN; i++) {
            float r0 = st[rb - i];
            float s  = fmaf(n0, r0, fmaf(n1, r1, n2 * r2));
            float yc = fmaf(tr, ya, fmaf(-dt, yb, s));
            st[kbase - i] = yc;
            yb = ya; ya = yc;
            r2 = r1; r1 = r0;
        }
    }
    __syncthreads();

    // writeback: scalar LDS (padded idx), STG.128 (global is aligned)
    float* ob = out + (size_t)b * LOUT;
#pragma unroll
    for (int it = 0; it < 4; it++) {
        int k = (tid + it * TPB) * 4;
        int i0 = IDX5(k);
        float4 v = make_float4(st[i0], st[i0 + 1], st[i0 + 2], st[i0 + 3]);
        *(float4*)(ob + k) = v;
    }
}

extern "C" void kernel_launch(void* const* d_in, const int* in_sizes, int n_in,
                              void* d_out, int out_size) {
    const float* x     = (const float*)d_in[0];
    const float* cond  = (const float*)d_in[1];
    const float* state = (const float*)d_in[2];
    const float* a_rg  = (const float*)d_in[3];
    const float* a_r1  = (const float*)d_in[4];
    const float* a_c1  = (const float*)d_in[5];
    const float* a_c2  = (const float*)d_in[6];
    const float* cw    = (const float*)d_in[7];
    const float* cb    = (const float*)d_in[8];

    int B = in_sizes[1];  // cond is [B,1]
    if (B > 4096) B = 4096;

    coeff_kernel<<<(B + 127) / 128, 128>>>(cond, cw, cb, a_rg, a_r1, a_c1, a_c2, B);
    filter_kernel<<<B, TPB>>>(x, state, (float*)d_out);
}

// round 16
// speedup vs baseline: 1.0138x; 1.0138x over previous
#include <cuda_runtime.h>
#include <math.h>

#define LOUT 2048
#define NFFT 4096
#define CLEN 32
#define NCH  128
#define TPB  128

// per batch: n0, n1, n2, tr, det (stride 8 floats)
__device__ float g_coef[4096 * 8];

// ---------------------------------------------------------------------------
// Coefficient kernel: closed-form circuit solve (fp64, tiny).
// ---------------------------------------------------------------------------
__global__ void coeff_kernel(const float* __restrict__ cond,
                             const float* __restrict__ cw,
                             const float* __restrict__ cb,
                             const float* __restrict__ a_rg,
                             const float* __restrict__ a_r1,
                             const float* __restrict__ a_c1,
                             const float* __restrict__ a_c2, int B) {
    int b = blockIdx.x * blockDim.x + threadIdx.x;
    if (b >= B) return;

    const double T = 1.0 / 44100.0;
    double sRG = (double)(1.f / (1.f + expf(-a_rg[0])));
    double sR1 = (double)(1.f / (1.f + expf(-a_r1[0])));
    double sC1 = (double)(1.f / (1.f + expf(-a_c1[0])));
    double sC2 = (double)(1.f / (1.f + expf(-a_c2[0])));
    double RG = (0.9 + 0.2 * sRG) * 1.0e6;
    double R1 = (0.99 + 0.02 * sR1) * 4.7e5;
    double C1 = (0.9 + 0.2 * sC1) * 3.3e-9;
    double C2 = (0.9 + 0.2 * sC2) * 1.0e-9;
    double Gr = 1.0 / R1, g1 = 2.0 * C1 / T, g2 = 2.0 * C2 / T;
    double G = g1 + Gr, h = g1 / G, iG = 1.0 / G, ig2 = 1.0 / g2;

    double Q00 = iG + ig2, Q01 = -ig2, Q11 = ig2;
    double Ux00 = -iG, Ux01 = 0.0, Ux10 = -ig2, Ux11 = ig2;
    double Ao00 = 2.0 * g1 * iG - 1.0, Ao11 = 1.0;
    double Uo0 = -ig2, Uo1 = ig2;
    double Uu0 = h;
    double Do1 = ig2;
    double Bo0 = 2.0 * g1 * (1.0 - h);
    double W000 = -2.0 * g1 * iG;
    double W010 = -2.0, W011 = 2.0;

    float zf  = cond[b] * cw[0] + cb[0];
    float pot = 1.f / (1.f + expf(-zf));
    float pf  = (powf(10.f, pot) - 1.f) / 9.f;
    pf = fminf(fmaxf(pf, 1e-4f), 1.f - 1e-4f);
    double p = (double)pf;

    double r00 = (1.0 - p) * RG + Q00, r01 = Q01, r11 = p * RG + Q11;
    double id  = 1.0 / (r00 * r11 - r01 * r01);
    double S00 = r11 * id, S01 = -r01 * id, S11 = r00 * id;

    double W00 = W000 * S00;
    double W01 = W000 * S01;
    double W10 = W010 * S00 + W011 * S01;
    double W11 = W010 * S01 + W011 * S11;

    double A00 = Ao00 - (W00 * Ux00 + W01 * Ux01);
    double A01 =       - (W00 * Ux10 + W01 * Ux11);
    double A10 =       - (W10 * Ux00 + W11 * Ux01);
    double A11 = Ao11 - (W10 * Ux10 + W11 * Ux11);
    double Bm0 = Bo0 - W00 * Uu0;
    double Bm1 =     - W10 * Uu0;
    double V0  = Uo0 * S00 + Uo1 * S01;
    double V1  = Uo0 * S01 + Uo1 * S11;
    double Dm0 =       - (V0 * Ux00 + V1 * Ux01);
    double Dm1 = Do1   - (V0 * Ux10 + V1 * Ux11);
    double Em  = -(V0 * Uu0);

    double tr  = A00 + A11;
    double det = A00 * A11 - A01 * A10;
    double E00 = A00 - Bm0 * Dm0, E01 = A01 - Bm0 * Dm1;
    double E10 = A10 - Bm1 * Dm0, E11 = A11 - Bm1 * Dm1;
    double trE = E00 + E11, detE = E00 * E11 - E01 * E10;

    float* cf = g_coef + b * 8;
    cf[0] = (float)Em;
    cf[1] = (float)(-trE - (Em - 1.0) * tr);
    cf[2] = (float)(detE + (Em - 1.0) * det);
    cf[3] = (float)tr;
    cf[4] = (float)det;
}

// ---------------------------------------------------------------------------
// Filter kernel: exact circular backward biquad via 128-chunk affine scan +
// 64-chunk replay. y overlaid into the first half of the st buffer:
//   replay reads padded idx >= IDX5(2048)=2112, writes idx <= IDX5(2047)=2110.
// Global side uses float4 (aligned); shared side is scalar (pad breaks 16B
// alignment of the padded index — that was the R4 trap).
// ---------------------------------------------------------------------------
#define IDX5(n) ((n) + ((n) >> 5))

__global__ void __launch_bounds__(TPB)
filter_kernel(const float* __restrict__ x, const float* __restrict__ state,
              float* __restrict__ out) {
    __shared__ float st[4226];            // IDX5(4097)=4225
    __shared__ float scanArr[NCH][6];
    __shared__ float warpTot[4][6];

    int b = blockIdx.x, tid = threadIdx.x;
    const float* cf = g_coef + b * 8;
    float n0 = cf[0], n1 = cf[1], n2 = cf[2], tr = cf[3], dt = cf[4];

    const float* stt = state + (size_t)b * NFFT + LOUT;  // state tail
    const float* xb  = x + (size_t)b * LOUT;

    // load periodic buffer: LDG.128, scalar STS (padded idx not 16B-aligned)
#pragma unroll
    for (int it = 0; it < 8; it++) {
        int n = (tid + it * TPB) * 4;
        float4 v = (n < LOUT) ? *(const float4*)(stt + n)
                              : *(const float4*)(xb + n - LOUT);
        int i0 = IDX5(n);                 // n..n+3 stay in one pad group
        st[i0] = v.x; st[i0 + 1] = v.y; st[i0 + 2] = v.z; st[i0 + 3] = v.w;
    }
    if (tid < 2) st[IDX5(NFFT + tid)] = stt[tid];
    __syncthreads();

    // Pass 1: chunk c = tid, 32 backward steps, zero IC, track affine map.
    int c = tid;
    int nhi = NFFT - 1 - CLEN * c;        // nhi ≡ 31 (mod 32): chunk in one pad group
    int off = IDX5(nhi);
    float v1 = st[IDX5(nhi + 1)], v2 = st[IDX5(nhi + 2)];
    float pa = 0.f, pb = 0.f;
    float ma0 = 1.f, ma1 = 0.f, mb0 = 0.f, mb1 = 1.f;
#pragma unroll
    for (int i = 0; i < CLEN; i++) {
        float v0 = st[off - i];
        float s  = fmaf(n0, v0, fmaf(n1, v1, n2 * v2));
        float pc = fmaf(tr, pa, fmaf(-dt, pb, s));
        float t0 = fmaf(tr, ma0, -dt * mb0);
        float t1 = fmaf(tr, ma1, -dt * mb1);
        mb0 = ma0; mb1 = ma1; ma0 = t0; ma1 = t1;
        pb = pa; pa = pc;
        v2 = v1; v1 = v0;
    }

    // Intra-warp inclusive affine scan (compose: self ∘ left).
    const unsigned fullm = 0xffffffffu;
    int lane = tid & 31;
#pragma unroll
    for (int d = 1; d < 32; d <<= 1) {
        float la0 = __shfl_up_sync(fullm, ma0, d);
        float la1 = __shfl_up_sync(fullm, ma1, d);
        float lb0 = __shfl_up_sync(fullm, mb0, d);
        float lb1 = __shfl_up_sync(fullm, mb1, d);
        float lp0 = __shfl_up_sync(fullm, pa, d);
        float lp1 = __shfl_up_sync(fullm, pb, d);
        if (lane >= d) {
            float na0 = ma0 * la0 + ma1 * lb0;
            float na1 = ma0 * la1 + ma1 * lb1;
            float nb0 = mb0 * la0 + mb1 * lb0;
            float nb1 = mb0 * la1 + mb1 * lb1;
            float np0 = ma0 * lp0 + ma1 * lp1 + pa;
            float np1 = mb0 * lp0 + mb1 * lp1 + pb;
            ma0 = na0; ma1 = na1; mb0 = nb0; mb1 = nb1; pa = np0; pb = np1;
        }
    }
    int w = tid >> 5;
    if (lane == 31) {
        warpTot[w][0] = ma0; warpTot[w][1] = ma1;
        warpTot[w][2] = mb0; warpTot[w][3] = mb1;
        warpTot[w][4] = pa;  warpTot[w][5] = pb;
    }
    __syncthreads();

    // cross-warp composition
    if (w > 0) {
        float LA0 = warpTot[0][0], LA1 = warpTot[0][1];
        float LB0 = warpTot[0][2], LB1 = warpTot[0][3];
        float LP0 = warpTot[0][4], LP1 = warpTot[0][5];
        for (int ww = 1; ww < w; ww++) {
            float t0 = warpTot[ww][0], t1 = warpTot[ww][1];
            float t2 = warpTot[ww][2], t3 = warpTot[ww][3];
            float t4 = warpTot[ww][4], t5 = warpTot[ww][5];
            float nA0 = t0 * LA0 + t1 * LB0, nA1 = t0 * LA1 + t1 * LB1;
            float nB0 = t2 * LA0 + t3 * LB0, nB1 = t2 * LA1 + t3 * LB1;
            float nP0 = t0 * LP0 + t1 * LP1 + t4;
            float nP1 = t2 * LP0 + t3 * LP1 + t5;
            LA0 = nA0; LA1 = nA1; LB0 = nB0; LB1 = nB1; LP0 = nP0; LP1 = nP1;
        }
        float na0 = ma0 * LA0 + ma1 * LB0;
        float na1 = ma0 * LA1 + ma1 * LB1;
        float nb0 = mb0 * LA0 + mb1 * LB0;
        float nb1 = mb0 * LA1 + mb1 * LB1;
        float np0 = ma0 * LP0 + ma1 * LP1 + pa;
        float np1 = mb0 * LP0 + mb1 * LP1 + pb;
        ma0 = na0; ma1 = na1; mb0 = nb0; mb1 = nb1; pa = np0; pb = np1;
    }
    scanArr[c][0] = ma0; scanArr[c][1] = ma1;
    scanArr[c][2] = mb0; scanArr[c][3] = mb1;
    scanArr[c][4] = pa;  scanArr[c][5] = pb;
    __syncthreads();

    // Replay: threads c<64 solve the periodic fixed point, get exact chunk IC,
    // re-run 32 steps and write y into st[IDX5(0..2047)] (disjoint from reads).
    if (c < 64) {
        float F00 = scanArr[NCH - 1][0], F01 = scanArr[NCH - 1][1];
        float F10 = scanArr[NCH - 1][2], F11 = scanArr[NCH - 1][3];
        float Pt0 = scanArr[NCH - 1][4], Pt1 = scanArr[NCH - 1][5];
        float aa = 1.f - F00, bb = -F01, cc = -F10, dd = 1.f - F11;
        float inv = 1.f / (aa * dd - bb * cc);
        float w0 = (dd * Pt0 - bb * Pt1) * inv;
        float w1 = (-cc * Pt0 + aa * Pt1) * inv;

        float vx, vy;
        if (c == 0) { vx = w0; vy = w1; }
        else {
            float e0 = scanArr[c - 1][0], e1 = scanArr[c - 1][1];
            float e2 = scanArr[c - 1][2], e3 = scanArr[c - 1][3];
            float e4 = scanArr[c - 1][4], e5 = scanArr[c - 1][5];
            vx = e0 * w0 + e1 * w1 + e4;
            vy = e2 * w0 + e3 * w1 + e5;
        }

        int rb  = IDX5(nhi);
        float r1 = st[IDX5(nhi + 1)], r2 = st[IDX5(nhi + 2)];
        float ya = vx, yb = vy;
        int kbase = IDX5(nhi - LOUT);     // same pad group (nhi-2048 ≡ 31 mod 32)
#pragma unroll
        for (int i = 0; i < CLEN; i++) {
            float r0 = st[rb - i];
            float s  = fmaf(n0, r0, fmaf(n1, r1, n2 * r2));
            float yc = fmaf(tr, ya, fmaf(-dt, yb, s));
            st[kbase - i] = yc;
            yb = ya; ya = yc;
            r2 = r1; r1 = r0;
        }
    }
    __syncthreads();

    // writeback: scalar LDS (padded idx), STG.128 (global is aligned)
    float* ob = out + (size_t)b * LOUT;
#pragma unroll
    for (int it = 0; it < 4; it++) {
        int k = (tid + it * TPB) * 4;
        int i0 = IDX5(k);
        float4 v = make_float4(st[i0], st[i0 + 1], st[i0 + 2], st[i0 + 3]);
        *(float4*)(ob + k) = v;
    }
}

extern "C" void kernel_launch(void* const* d_in, const int* in_sizes, int n_in,
                              void* d_out, int out_size) {
    const float* x     = (const float*)d_in[0];
    const float* cond  = (const float*)d_in[1];
    const float* state = (const float*)d_in[2];
    const float* a_rg  = (const float*)d_in[3];
    const float* a_r1  = (const float*)d_in[4];
    const float* a_c1  = (const float*)d_in[5];
    const float* a_c2  = (const float*)d_in[6];
    const float* cw    = (const float*)d_in[7];
    const float* cb    = (const float*)d_in[8];

    int B = in_sizes[1];  // cond is [B,1]
    if (B > 4096) B = 4096;

    coeff_kernel<<<(B + 127) / 128, 128>>>(cond, cw, cb, a_rg, a_r1, a_c1, a_c2, B);
    filter_kernel<<<B, TPB>>>(x, state, (float*)d_out);
}